// round 14
// baseline (speedup 1.0000x reference)
#include <cuda_runtime.h>
#include <cuda_bf16.h>
#include <cstdint>

// ============================================================================
// MeToken: z_q = softmax(topk3_gated(x @ cb^T) / 0.01) @ cb
//
// Identity (non-topk gated scores are 0, not -inf):
//   m = max(top1, 0), w_k = exp((s_k-m)/tau), b = exp(-m/tau)
//   Z   = w0+w1+w2 + (C-K)*b
//   z_q = (w0*cb0 + w1*cb1 + w2*cb2 + b*(colsum(cb) - cb0-cb1-cb2)) / Z
//
// R14: rank-select finalize. The two serial merge stages are replaced by a
// parallel rank computation (each thread counts keys outranking its own;
// rank<8 -> candidate pool). GEMM (R13 half-phase overlap) unchanged.
// ============================================================================

#define N_ROWS 8192
#define DIM 128
#define N_CODES 16384
#define TOPK 3

#define MT 128
#define NT 128                          // codes per B-subtile
#define TILES_PER_GROUP 8
#define GROUP_CODES (NT * TILES_PER_GROUP)   // 1024
#define NGROUPS (N_CODES / GROUP_CODES)      // 16
#define MTILES (N_ROWS / MT)                 // 64
#define CAND 8
#define STRIDE_B 272                    // bytes per smem row (136 bf16)
#define A_BYTES (128 * STRIDE_B)        // 34816
#define B_BYTES (128 * STRIDE_B)        // 34816
#define GEMM_SMEM (A_BYTES + 2 * B_BYTES)    // 104448

#define NEG_SENT (-3.0e38f)

// ---------------- scratch (no allocs allowed) ----------------
__device__ __nv_bfloat16 g_xb[N_ROWS * DIM];
__device__ __nv_bfloat16 g_cbb[N_CODES * DIM];
__device__ float g_part_cbsum[256 * DIM];
__device__ float g_cbsum[DIM];
__device__ float g_ckey[(size_t)N_ROWS * NGROUPS * CAND];   // float keys (idx in low bits)

// ---------------- helpers ----------------
__device__ __forceinline__ uint32_t smem_u32(const void* p) {
    uint32_t a;
    asm("{ .reg .u64 t; cvta.to.shared.u64 t, %1; cvt.u32.u64 %0, t; }" : "=r"(a) : "l"(p));
    return a;
}
__device__ __forceinline__ void cp_async16(uint32_t dst, const void* src) {
    asm volatile("cp.async.cg.shared.global [%0], [%1], 16;" :: "r"(dst), "l"(src) : "memory");
}
__device__ __forceinline__ void cp_commit() {
    asm volatile("cp.async.commit_group;" ::: "memory");
}
__device__ __forceinline__ void cp_wait1() {
    asm volatile("cp.async.wait_group 1;" ::: "memory");
}
__device__ __forceinline__ void cp_wait0() {
    asm volatile("cp.async.wait_group 0;" ::: "memory");
}
__device__ __forceinline__ void ldsm_x4(uint32_t& r0, uint32_t& r1, uint32_t& r2, uint32_t& r3,
                                        uint32_t addr) {
    asm volatile("ldmatrix.sync.aligned.m8n8.x4.shared.b16 {%0,%1,%2,%3}, [%4];"
                 : "=r"(r0), "=r"(r1), "=r"(r2), "=r"(r3) : "r"(addr));
}
__device__ __forceinline__ void mma16816(float c[4], const uint32_t a[4], const uint32_t b[2]) {
    asm volatile(
        "mma.sync.aligned.m16n8k16.row.col.f32.bf16.bf16.f32 "
        "{%0,%1,%2,%3}, {%4,%5,%6,%7}, {%8,%9}, {%0,%1,%2,%3};"
        : "+f"(c[0]), "+f"(c[1]), "+f"(c[2]), "+f"(c[3])
        : "r"(a[0]), "r"(a[1]), "r"(a[2]), "r"(a[3]), "r"(b[0]), "r"(b[1]));
}

// float key: low 10 mantissa bits replaced by group-local code index (1 LOP3)
__device__ __forceinline__ float pack_keyf(float s, int lidx) {
    return __uint_as_float((__float_as_uint(s) & 0xFFFFFC00u) | (uint32_t)lidx);
}
// branchless top-3 fold: 5 FMNMX, no branches
__device__ __forceinline__ void fold3f(float k, float v[3]) {
    const float t0 = fmaxf(v[0], k);
    const float m0 = fminf(v[0], k);
    const float t1 = fmaxf(v[1], m0);
    const float m1 = fminf(v[1], m0);
    const float t2 = fmaxf(v[2], m1);
    v[0] = t0; v[1] = t1; v[2] = t2;
}
__device__ __forceinline__ void insk8f(float k, float v[8]) {
    if (k <= v[7]) return;
    v[7] = k;
#pragma unroll
    for (int t = 7; t > 0; --t)
        if (v[t] > v[t - 1]) { float tv = v[t]; v[t] = v[t - 1]; v[t - 1] = tv; }
}
__device__ __forceinline__ void ins3f(float s, int c, float v[3], int ix[3]) {
    if (s > v[2]) {
        if (s > v[1]) {
            v[2] = v[1]; ix[2] = ix[1];
            if (s > v[0]) { v[1] = v[0]; ix[1] = ix[0]; v[0] = s; ix[0] = c; }
            else          { v[1] = s;    ix[1] = c; }
        } else { v[2] = s; ix[2] = c; }
    }
}

// ---------------------------------------------------------------------------
// 1) fused converts (+ cb partial column sums)
// ---------------------------------------------------------------------------
__global__ void __launch_bounds__(256)
convert_all_kernel(const float* __restrict__ x, const float* __restrict__ cb) {
    if (blockIdx.x < 1024) {
        const int i = (blockIdx.x * 256 + threadIdx.x) * 4;
        const float4 v = *(const float4*)(x + i);
        __nv_bfloat162* o = (__nv_bfloat162*)(g_xb + i);
        o[0] = __nv_bfloat162(__float2bfloat16_rn(v.x), __float2bfloat16_rn(v.y));
        o[1] = __nv_bfloat162(__float2bfloat16_rn(v.z), __float2bfloat16_rn(v.w));
    } else {
        const int b = blockIdx.x - 1024;          // 128 cb blocks, 128 codes each
        const int d = threadIdx.x & 127;          // column
        const int h = threadIdx.x >> 7;           // half: rows [h*64, h*64+64)
        const float* p = cb + ((size_t)b * 128 + h * 64) * DIM + d;
        __nv_bfloat16* q = g_cbb + ((size_t)b * 128 + h * 64) * DIM + d;
        float s = 0.0f;
#pragma unroll 8
        for (int c = 0; c < 64; ++c) {
            const float v = p[(size_t)c * DIM];
            s += v;
            q[(size_t)c * DIM] = __float2bfloat16_rn(v);
        }
        g_part_cbsum[(b * 2 + h) * DIM + d] = s;
    }
}
__global__ void cbsum_comb_kernel() {
    const int d = threadIdx.x;
    float s = 0.0f;
#pragma unroll 8
    for (int b = 0; b < 256; ++b) s += g_part_cbsum[b * DIM + d];
    g_cbsum[d] = s;
}

// ---------------------------------------------------------------------------
// 2) multi-tile mma.sync GEMM, 2 CTAs/SM, half-phase fold overlap (R13)
// ---------------------------------------------------------------------------
__global__ void __launch_bounds__(256, 2)
gemm_topk_kernel(const __nv_bfloat16* __restrict__ xb,
                 const __nv_bfloat16* __restrict__ cbb) {
    extern __shared__ __align__(16) char smem[];
    const uint32_t sbase = smem_u32(smem);
    const uint32_t sA = sbase;
    const uint32_t sB[2] = { sbase + A_BYTES, sbase + A_BYTES + B_BYTES };

    const int tid = threadIdx.x;
    const int wid = tid >> 5, lane = tid & 31;
    const int g = lane >> 2, tig = lane & 3;
    const int wm = wid & 3, wn = wid >> 2;       // 4M x 2N

    const int row0  = blockIdx.x * MT;
    const int code0 = blockIdx.y * GROUP_CODES;

    const uint4* gx = (const uint4*)(xb + (size_t)row0 * DIM);
    const uint4* gc = (const uint4*)(cbb + (size_t)code0 * DIM);

    // ---- prologue: A + B0 ----
#pragma unroll
    for (int i = tid; i < 128 * 16; i += 256) {
        const int r = i >> 4, kc = i & 15;
        cp_async16(sA + r * STRIDE_B + kc * 16, gx + r * 16 + kc);
    }
#pragma unroll
    for (int i = tid; i < 128 * 16; i += 256) {
        const int r = i >> 4, kc = i & 15;
        cp_async16(sB[0] + r * STRIDE_B + kc * 16, gc + r * 16 + kc);
    }
    cp_commit();

    // float top-3 keys for 4 owned rows
    float kv[4][3];
#pragma unroll
    for (int t = 0; t < 4; ++t)
#pragma unroll
        for (int s = 0; s < 3; ++s) kv[t][s] = NEG_SENT;

    // ldmatrix per-lane addressing
    const int aq = lane >> 3;
    const uint32_t fragRow = (uint32_t)((lane & 7) + (aq & 1) * 8);
    const uint32_t fragCol = (uint32_t)((aq >> 1) * 16);
    const uint32_t aOff = (uint32_t)(wm * 32) * STRIDE_B + fragRow * STRIDE_B + fragCol;
    const uint32_t bFragRow = (uint32_t)((lane & 7) + (aq >> 1) * 8);
    const uint32_t bFragCol = (uint32_t)((aq & 1) * 16);
    const uint32_t bOff = (uint32_t)(wn * 64) * STRIDE_B + bFragRow * STRIDE_B + bFragCol;
    const int colb = wn * 64 + tig * 2;          // lane's column base within tile

    // two half-tile accumulator banks (32 scores each), ping-ponged
    float accP[2][4][4], accQ[2][4][4];

#define HALF_PHASE(T, H, CUR, PREV, PBASE, DOFOLD)                             \
    {                                                                          \
        _Pragma("unroll")                                                      \
        for (int i = 0; i < 2; ++i)                                            \
            _Pragma("unroll")                                                  \
            for (int jj = 0; jj < 4; ++jj)                                     \
                _Pragma("unroll")                                              \
                for (int c = 0; c < 4; ++c) CUR[i][jj][c] = 0.0f;              \
        const uint32_t aBt = sA + aOff;                                        \
        const uint32_t bBt = sB[(T) & 1] + bOff                                \
                           + (uint32_t)(32 * (H)) * STRIDE_B;                  \
        _Pragma("unroll")                                                      \
        for (int ks = 0; ks < 8; ++ks) {                                       \
            const uint32_t kOff = ks * 32;                                     \
            uint32_t a[2][4];                                                  \
            _Pragma("unroll")                                                  \
            for (int i = 0; i < 2; ++i)                                        \
                ldsm_x4(a[i][0], a[i][1], a[i][2], a[i][3],                    \
                        aBt + (uint32_t)(16 * i) * STRIDE_B + kOff);           \
            uint32_t b[4][2];                                                  \
            _Pragma("unroll")                                                  \
            for (int jp = 0; jp < 2; ++jp)                                     \
                ldsm_x4(b[2 * jp][0], b[2 * jp][1],                            \
                        b[2 * jp + 1][0], b[2 * jp + 1][1],                    \
                        bBt + (uint32_t)(16 * jp) * STRIDE_B + kOff);          \
            _Pragma("unroll")                                                  \
            for (int i = 0; i < 2; ++i)                                        \
                _Pragma("unroll")                                              \
                for (int jj = 0; jj < 4; ++jj)                                 \
                    mma16816(CUR[i][jj], a[i], b[jj]);                         \
            if (DOFOLD) {                                                      \
                const int fi = ks >> 2, fj = ks & 3;                           \
                const int c0f = (PBASE) + fj * 8;                              \
                fold3f(pack_keyf(PREV[fi][fj][0], c0f),     kv[2 * fi]);       \
                fold3f(pack_keyf(PREV[fi][fj][1], c0f + 1), kv[2 * fi]);       \
                fold3f(pack_keyf(PREV[fi][fj][2], c0f),     kv[2 * fi + 1]);   \
                fold3f(pack_keyf(PREV[fi][fj][3], c0f + 1), kv[2 * fi + 1]);   \
            }                                                                  \
        }                                                                      \
    }

#define TILE_STEP(T, FOLD0)                                                    \
    {                                                                          \
        __syncthreads();                                                       \
        if ((T) + 1 < TILES_PER_GROUP) {                                       \
            const uint4* gt = gc + (size_t)((T) + 1) * 2048;                   \
            const uint32_t dst = sB[((T) + 1) & 1];                            \
            _Pragma("unroll")                                                  \
            for (int i2 = tid; i2 < 2048; i2 += 256) {                         \
                const int r2 = i2 >> 4, kc2 = i2 & 15;                         \
                cp_async16(dst + r2 * STRIDE_B + kc2 * 16, gt + r2 * 16 + kc2);\
            }                                                                  \
            cp_commit(); cp_wait1();                                           \
        } else { cp_wait0(); }                                                 \
        __syncthreads();                                                       \
        HALF_PHASE(T, 0, accP, accQ, ((T) - 1) * NT + 32 + colb, FOLD0)        \
        HALF_PHASE(T, 1, accQ, accP, (T) * NT + colb, true)                    \
    }

    TILE_STEP(0, false)
    TILE_STEP(1, true)
    TILE_STEP(2, true)
    TILE_STEP(3, true)
    TILE_STEP(4, true)
    TILE_STEP(5, true)
    TILE_STEP(6, true)
    TILE_STEP(7, true)
#undef TILE_STEP
#undef HALF_PHASE

    // epilogue fold: half (7,1) lives in accQ, base = 7*NT + 32 + colb
#pragma unroll
    for (int jj = 0; jj < 4; ++jj) {
        const int c0f = 7 * NT + 32 + colb + jj * 8;
        fold3f(pack_keyf(accQ[0][jj][0], c0f),     kv[0]);
        fold3f(pack_keyf(accQ[0][jj][1], c0f + 1), kv[0]);
        fold3f(pack_keyf(accQ[0][jj][2], c0f),     kv[1]);
        fold3f(pack_keyf(accQ[0][jj][3], c0f + 1), kv[1]);
        fold3f(pack_keyf(accQ[1][jj][0], c0f),     kv[2]);
        fold3f(pack_keyf(accQ[1][jj][1], c0f + 1), kv[2]);
        fold3f(pack_keyf(accQ[1][jj][2], c0f),     kv[3]);
        fold3f(pack_keyf(accQ[1][jj][3], c0f + 1), kv[3]);
    }

    // ---- CTA merge: 24 keys/row -> top-8 keys ----
    __syncthreads();
    float* skey = (float*)smem;                  // [128][24] = 12288 B
#pragma unroll
    for (int s4 = 0; s4 < 4; ++s4) {
        const int r = wm * 32 + (s4 >> 1) * 16 + (s4 & 1) * 8 + g;
        const int slot = (wn * 4 + tig) * 3;
#pragma unroll
        for (int s = 0; s < 3; ++s) skey[r * 24 + slot + s] = kv[s4][s];
    }
    __syncthreads();

    if (tid < 128) {
        const int r = tid;
        float v[8];
#pragma unroll
        for (int s = 0; s < 8; ++s) v[s] = NEG_SENT;
#pragma unroll 1
        for (int q = 0; q < 24; ++q) insk8f(skey[r * 24 + q], v);
        const size_t base = ((size_t)(row0 + r) * NGROUPS + blockIdx.y) * CAND;
#pragma unroll
        for (int s = 0; s < 8; ++s) g_ckey[base + s] = v[s];
    }
}

// ---------------------------------------------------------------------------
// 3) finalize: parallel rank-select top-8, exact fp32 rescore, softmax
// ---------------------------------------------------------------------------
__global__ void __launch_bounds__(128)
finalize_kernel(const float* __restrict__ x, const float* __restrict__ cb,
                float* __restrict__ out) {
    const int row = blockIdx.x;
    const int tid = threadIdx.x;
    const int wid = tid >> 5, lid = tid & 31;

    __shared__ float sk[NGROUPS * CAND];         // 128 keys
    __shared__ int   pick[8];
    __shared__ float sex[8];
    __shared__ float sw[4];
    __shared__ int   sid[3];

    const size_t cbase = (size_t)row * NGROUPS * CAND;
    sk[tid] = g_ckey[cbase + tid];
    __syncthreads();

    // parallel rank-select: thread tid owns key sk[tid]; rank = #keys that
    // outrank it (ties broken by slot index -> unique ranks). rank<8 -> pool.
    {
        const float kme = sk[tid];
        int rank = 0;
#pragma unroll 16
        for (int q = 0; q < NGROUPS * CAND; ++q) {
            const float kq = sk[q];
            rank += (int)((kq > kme) | ((kq == kme) & (q < tid)));
        }
        if (rank < CAND) {
            const int code = (tid >> 3) * GROUP_CODES + (int)(__float_as_uint(kme) & 1023u);
            pick[rank] = code;
        }
    }
    __syncthreads();

    // exact fp32 rescore: warp w handles candidates 2w, 2w+1
    const float4 xa = ((const float4*)(x + (size_t)row * DIM))[lid];
#pragma unroll
    for (int t = 0; t < 2; ++t) {
        const int cc = wid * 2 + t;
        const int c = pick[cc];
        const float4 ca = ((const float4*)(cb + (size_t)c * DIM))[lid];
        float p = xa.x * ca.x;
        p = fmaf(xa.y, ca.y, p);
        p = fmaf(xa.z, ca.z, p);
        p = fmaf(xa.w, ca.w, p);
#pragma unroll
        for (int o = 16; o > 0; o >>= 1) p += __shfl_xor_sync(0xFFFFFFFFu, p, o);
        if (lid == 0) sex[cc] = p;
    }
    __syncthreads();

    if (tid == 0) {
        float v[3] = { NEG_SENT, NEG_SENT, NEG_SENT };
        int ix[3] = { 0, 0, 0 };
#pragma unroll
        for (int q = 0; q < 8; ++q) ins3f(sex[q], pick[q], v, ix);
        const float INV_TAU = 100.0f;
        const float m  = fmaxf(v[0], 0.0f);
        const float w0 = expf((v[0] - m) * INV_TAU);
        const float w1 = expf((v[1] - m) * INV_TAU);
        const float w2 = expf((v[2] - m) * INV_TAU);
        const float b  = expf(-m * INV_TAU);
        const float Z  = w0 + w1 + w2 + b * (float)(N_CODES - TOPK);
        const float invZ = 1.0f / Z;
        sw[0] = w0 * invZ; sw[1] = w1 * invZ; sw[2] = w2 * invZ; sw[3] = b * invZ;
        sid[0] = ix[0]; sid[1] = ix[1]; sid[2] = ix[2];
    }
    __syncthreads();

    const int d = tid;
    const float c0 = cb[(size_t)sid[0] * DIM + d];
    const float c1 = cb[(size_t)sid[1] * DIM + d];
    const float c2 = cb[(size_t)sid[2] * DIM + d];
    out[(size_t)row * DIM + d] =
        sw[0] * c0 + sw[1] * c1 + sw[2] * c2 + sw[3] * (g_cbsum[d] - c0 - c1 - c2);
}

// ---------------------------------------------------------------------------
extern "C" void kernel_launch(void* const* d_in, const int* in_sizes, int n_in,
                              void* d_out, int out_size) {
    const float* x  = (const float*)d_in[0];
    const float* cb = (const float*)d_in[1];
    if (n_in >= 2 && in_sizes[0] == N_CODES * DIM && in_sizes[1] == N_ROWS * DIM) {
        x  = (const float*)d_in[1];
        cb = (const float*)d_in[0];
    }
    float* out = (float*)d_out;

    cudaFuncSetAttribute(gemm_topk_kernel,
                         cudaFuncAttributeMaxDynamicSharedMemorySize, GEMM_SMEM);

    __nv_bfloat16 *xb_p, *cbb_p;
    cudaGetSymbolAddress((void**)&xb_p, g_xb);
    cudaGetSymbolAddress((void**)&cbb_p, g_cbb);

    convert_all_kernel<<<1152, 256>>>(x, cb);
    cbsum_comb_kernel<<<1, 128>>>();
    gemm_topk_kernel<<<dim3(MTILES, NGROUPS), 256, GEMM_SMEM>>>(xb_p, cbb_p);
    finalize_kernel<<<N_ROWS, 128>>>(x, cb, out);
}

// round 15
// speedup vs baseline: 1.6195x; 1.6195x over previous
#include <cuda_runtime.h>
#include <cuda_bf16.h>
#include <cstdint>

// ============================================================================
// MeToken: z_q = softmax(topk3_gated(x @ cb^T) / 0.01) @ cb
//
// Identity (non-topk gated scores are 0, not -inf):
//   m = max(top1, 0), w_k = exp((s_k-m)/tau), b = exp(-m/tau)
//   Z   = w0+w1+w2 + (C-K)*b
//   z_q = (w0*cb0 + w1*cb1 + w2*cb2 + b*(colsum(cb) - cb0-cb1-cb2)) / Z
//
// R15 = R13 (best measured) + parallel stage-2 in finalize:
// stage-1 keeps the measured-cheap 8x16 branchy merge (128 -> 64 keys);
// stage-2's serial 64-key single-thread merge becomes a 64-thread
// rank-select (64 broadcast comparisons each, unique ranks by tie-break).
// ============================================================================

#define N_ROWS 8192
#define DIM 128
#define N_CODES 16384
#define TOPK 3

#define MT 128
#define NT 128                          // codes per B-subtile
#define TILES_PER_GROUP 8
#define GROUP_CODES (NT * TILES_PER_GROUP)   // 1024
#define NGROUPS (N_CODES / GROUP_CODES)      // 16
#define MTILES (N_ROWS / MT)                 // 64
#define CAND 8
#define STRIDE_B 272                    // bytes per smem row (136 bf16)
#define A_BYTES (128 * STRIDE_B)        // 34816
#define B_BYTES (128 * STRIDE_B)        // 34816
#define GEMM_SMEM (A_BYTES + 2 * B_BYTES)    // 104448

#define NEG_SENT (-3.0e38f)

// ---------------- scratch (no allocs allowed) ----------------
__device__ __nv_bfloat16 g_xb[N_ROWS * DIM];
__device__ __nv_bfloat16 g_cbb[N_CODES * DIM];
__device__ float g_part_cbsum[256 * DIM];
__device__ float g_cbsum[DIM];
__device__ float g_ckey[(size_t)N_ROWS * NGROUPS * CAND];   // float keys (idx in low bits)

// ---------------- helpers ----------------
__device__ __forceinline__ uint32_t smem_u32(const void* p) {
    uint32_t a;
    asm("{ .reg .u64 t; cvta.to.shared.u64 t, %1; cvt.u32.u64 %0, t; }" : "=r"(a) : "l"(p));
    return a;
}
__device__ __forceinline__ void cp_async16(uint32_t dst, const void* src) {
    asm volatile("cp.async.cg.shared.global [%0], [%1], 16;" :: "r"(dst), "l"(src) : "memory");
}
__device__ __forceinline__ void cp_commit() {
    asm volatile("cp.async.commit_group;" ::: "memory");
}
__device__ __forceinline__ void cp_wait1() {
    asm volatile("cp.async.wait_group 1;" ::: "memory");
}
__device__ __forceinline__ void cp_wait0() {
    asm volatile("cp.async.wait_group 0;" ::: "memory");
}
__device__ __forceinline__ void ldsm_x4(uint32_t& r0, uint32_t& r1, uint32_t& r2, uint32_t& r3,
                                        uint32_t addr) {
    asm volatile("ldmatrix.sync.aligned.m8n8.x4.shared.b16 {%0,%1,%2,%3}, [%4];"
                 : "=r"(r0), "=r"(r1), "=r"(r2), "=r"(r3) : "r"(addr));
}
__device__ __forceinline__ void mma16816(float c[4], const uint32_t a[4], const uint32_t b[2]) {
    asm volatile(
        "mma.sync.aligned.m16n8k16.row.col.f32.bf16.bf16.f32 "
        "{%0,%1,%2,%3}, {%4,%5,%6,%7}, {%8,%9}, {%0,%1,%2,%3};"
        : "+f"(c[0]), "+f"(c[1]), "+f"(c[2]), "+f"(c[3])
        : "r"(a[0]), "r"(a[1]), "r"(a[2]), "r"(a[3]), "r"(b[0]), "r"(b[1]));
}

// float key: low 10 mantissa bits replaced by group-local code index (1 LOP3)
__device__ __forceinline__ float pack_keyf(float s, int lidx) {
    return __uint_as_float((__float_as_uint(s) & 0xFFFFFC00u) | (uint32_t)lidx);
}
// branchless top-3 fold: 5 FMNMX, no branches
__device__ __forceinline__ void fold3f(float k, float v[3]) {
    const float t0 = fmaxf(v[0], k);
    const float m0 = fminf(v[0], k);
    const float t1 = fmaxf(v[1], m0);
    const float m1 = fminf(v[1], m0);
    const float t2 = fmaxf(v[2], m1);
    v[0] = t0; v[1] = t1; v[2] = t2;
}
__device__ __forceinline__ void insk8f(float k, float v[8]) {
    if (k <= v[7]) return;
    v[7] = k;
#pragma unroll
    for (int t = 7; t > 0; --t)
        if (v[t] > v[t - 1]) { float tv = v[t]; v[t] = v[t - 1]; v[t - 1] = tv; }
}
// keyed (float key, code) top-8 insert for finalize stage-1
__device__ __forceinline__ void insp8f(float k, int c, float v[8], int ix[8]) {
    if (k <= v[7]) return;
    v[7] = k; ix[7] = c;
#pragma unroll
    for (int t = 7; t > 0; --t) {
        if (v[t] > v[t - 1]) {
            float tv = v[t]; v[t] = v[t - 1]; v[t - 1] = tv;
            int ti = ix[t]; ix[t] = ix[t - 1]; ix[t - 1] = ti;
        }
    }
}
__device__ __forceinline__ void ins3f(float s, int c, float v[3], int ix[3]) {
    if (s > v[2]) {
        if (s > v[1]) {
            v[2] = v[1]; ix[2] = ix[1];
            if (s > v[0]) { v[1] = v[0]; ix[1] = ix[0]; v[0] = s; ix[0] = c; }
            else          { v[1] = s;    ix[1] = c; }
        } else { v[2] = s; ix[2] = c; }
    }
}

// ---------------------------------------------------------------------------
// 1) fused converts (+ cb partial column sums)
// ---------------------------------------------------------------------------
__global__ void __launch_bounds__(256)
convert_all_kernel(const float* __restrict__ x, const float* __restrict__ cb) {
    if (blockIdx.x < 1024) {
        const int i = (blockIdx.x * 256 + threadIdx.x) * 4;
        const float4 v = *(const float4*)(x + i);
        __nv_bfloat162* o = (__nv_bfloat162*)(g_xb + i);
        o[0] = __nv_bfloat162(__float2bfloat16_rn(v.x), __float2bfloat16_rn(v.y));
        o[1] = __nv_bfloat162(__float2bfloat16_rn(v.z), __float2bfloat16_rn(v.w));
    } else {
        const int b = blockIdx.x - 1024;          // 128 cb blocks, 128 codes each
        const int d = threadIdx.x & 127;          // column
        const int h = threadIdx.x >> 7;           // half: rows [h*64, h*64+64)
        const float* p = cb + ((size_t)b * 128 + h * 64) * DIM + d;
        __nv_bfloat16* q = g_cbb + ((size_t)b * 128 + h * 64) * DIM + d;
        float s = 0.0f;
#pragma unroll 8
        for (int c = 0; c < 64; ++c) {
            const float v = p[(size_t)c * DIM];
            s += v;
            q[(size_t)c * DIM] = __float2bfloat16_rn(v);
        }
        g_part_cbsum[(b * 2 + h) * DIM + d] = s;
    }
}
__global__ void cbsum_comb_kernel() {
    const int d = threadIdx.x;
    float s = 0.0f;
#pragma unroll 8
    for (int b = 0; b < 256; ++b) s += g_part_cbsum[b * DIM + d];
    g_cbsum[d] = s;
}

// ---------------------------------------------------------------------------
// 2) multi-tile mma.sync GEMM, 2 CTAs/SM, half-phase fold overlap (R13)
// ---------------------------------------------------------------------------
__global__ void __launch_bounds__(256, 2)
gemm_topk_kernel(const __nv_bfloat16* __restrict__ xb,
                 const __nv_bfloat16* __restrict__ cbb) {
    extern __shared__ __align__(16) char smem[];
    const uint32_t sbase = smem_u32(smem);
    const uint32_t sA = sbase;
    const uint32_t sB[2] = { sbase + A_BYTES, sbase + A_BYTES + B_BYTES };

    const int tid = threadIdx.x;
    const int wid = tid >> 5, lane = tid & 31;
    const int g = lane >> 2, tig = lane & 3;
    const int wm = wid & 3, wn = wid >> 2;       // 4M x 2N

    const int row0  = blockIdx.x * MT;
    const int code0 = blockIdx.y * GROUP_CODES;

    const uint4* gx = (const uint4*)(xb + (size_t)row0 * DIM);
    const uint4* gc = (const uint4*)(cbb + (size_t)code0 * DIM);

    // ---- prologue: A + B0 ----
#pragma unroll
    for (int i = tid; i < 128 * 16; i += 256) {
        const int r = i >> 4, kc = i & 15;
        cp_async16(sA + r * STRIDE_B + kc * 16, gx + r * 16 + kc);
    }
#pragma unroll
    for (int i = tid; i < 128 * 16; i += 256) {
        const int r = i >> 4, kc = i & 15;
        cp_async16(sB[0] + r * STRIDE_B + kc * 16, gc + r * 16 + kc);
    }
    cp_commit();

    // float top-3 keys for 4 owned rows
    float kv[4][3];
#pragma unroll
    for (int t = 0; t < 4; ++t)
#pragma unroll
        for (int s = 0; s < 3; ++s) kv[t][s] = NEG_SENT;

    // ldmatrix per-lane addressing
    const int aq = lane >> 3;
    const uint32_t fragRow = (uint32_t)((lane & 7) + (aq & 1) * 8);
    const uint32_t fragCol = (uint32_t)((aq >> 1) * 16);
    const uint32_t aOff = (uint32_t)(wm * 32) * STRIDE_B + fragRow * STRIDE_B + fragCol;
    const uint32_t bFragRow = (uint32_t)((lane & 7) + (aq >> 1) * 8);
    const uint32_t bFragCol = (uint32_t)((aq & 1) * 16);
    const uint32_t bOff = (uint32_t)(wn * 64) * STRIDE_B + bFragRow * STRIDE_B + bFragCol;
    const int colb = wn * 64 + tig * 2;          // lane's column base within tile

    // two half-tile accumulator banks (32 scores each), ping-ponged
    float accP[2][4][4], accQ[2][4][4];

#define HALF_PHASE(T, H, CUR, PREV, PBASE, DOFOLD)                             \
    {                                                                          \
        _Pragma("unroll")                                                      \
        for (int i = 0; i < 2; ++i)                                            \
            _Pragma("unroll")                                                  \
            for (int jj = 0; jj < 4; ++jj)                                     \
                _Pragma("unroll")                                              \
                for (int c = 0; c < 4; ++c) CUR[i][jj][c] = 0.0f;              \
        const uint32_t aBt = sA + aOff;                                        \
        const uint32_t bBt = sB[(T) & 1] + bOff                                \
                           + (uint32_t)(32 * (H)) * STRIDE_B;                  \
        _Pragma("unroll")                                                      \
        for (int ks = 0; ks < 8; ++ks) {                                       \
            const uint32_t kOff = ks * 32;                                     \
            uint32_t a[2][4];                                                  \
            _Pragma("unroll")                                                  \
            for (int i = 0; i < 2; ++i)                                        \
                ldsm_x4(a[i][0], a[i][1], a[i][2], a[i][3],                    \
                        aBt + (uint32_t)(16 * i) * STRIDE_B + kOff);           \
            uint32_t b[4][2];                                                  \
            _Pragma("unroll")                                                  \
            for (int jp = 0; jp < 2; ++jp)                                     \
                ldsm_x4(b[2 * jp][0], b[2 * jp][1],                            \
                        b[2 * jp + 1][0], b[2 * jp + 1][1],                    \
                        bBt + (uint32_t)(16 * jp) * STRIDE_B + kOff);          \
            _Pragma("unroll")                                                  \
            for (int i = 0; i < 2; ++i)                                        \
                _Pragma("unroll")                                              \
                for (int jj = 0; jj < 4; ++jj)                                 \
                    mma16816(CUR[i][jj], a[i], b[jj]);                         \
            if (DOFOLD) {                                                      \
                const int fi = ks >> 2, fj = ks & 3;                           \
                const int c0f = (PBASE) + fj * 8;                              \
                fold3f(pack_keyf(PREV[fi][fj][0], c0f),     kv[2 * fi]);       \
                fold3f(pack_keyf(PREV[fi][fj][1], c0f + 1), kv[2 * fi]);       \
                fold3f(pack_keyf(PREV[fi][fj][2], c0f),     kv[2 * fi + 1]);   \
                fold3f(pack_keyf(PREV[fi][fj][3], c0f + 1), kv[2 * fi + 1]);   \
            }                                                                  \
        }                                                                      \
    }

#define TILE_STEP(T, FOLD0)                                                    \
    {                                                                          \
        __syncthreads();                                                       \
        if ((T) + 1 < TILES_PER_GROUP) {                                       \
            const uint4* gt = gc + (size_t)((T) + 1) * 2048;                   \
            const uint32_t dst = sB[((T) + 1) & 1];                            \
            _Pragma("unroll")                                                  \
            for (int i2 = tid; i2 < 2048; i2 += 256) {                         \
                const int r2 = i2 >> 4, kc2 = i2 & 15;                         \
                cp_async16(dst + r2 * STRIDE_B + kc2 * 16, gt + r2 * 16 + kc2);\
            }                                                                  \
            cp_commit(); cp_wait1();                                           \
        } else { cp_wait0(); }                                                 \
        __syncthreads();                                                       \
        HALF_PHASE(T, 0, accP, accQ, ((T) - 1) * NT + 32 + colb, FOLD0)        \
        HALF_PHASE(T, 1, accQ, accP, (T) * NT + colb, true)                    \
    }

    TILE_STEP(0, false)
    TILE_STEP(1, true)
    TILE_STEP(2, true)
    TILE_STEP(3, true)
    TILE_STEP(4, true)
    TILE_STEP(5, true)
    TILE_STEP(6, true)
    TILE_STEP(7, true)
#undef TILE_STEP
#undef HALF_PHASE

    // epilogue fold: half (7,1) lives in accQ, base = 7*NT + 32 + colb
#pragma unroll
    for (int jj = 0; jj < 4; ++jj) {
        const int c0f = 7 * NT + 32 + colb + jj * 8;
        fold3f(pack_keyf(accQ[0][jj][0], c0f),     kv[0]);
        fold3f(pack_keyf(accQ[0][jj][1], c0f + 1), kv[0]);
        fold3f(pack_keyf(accQ[0][jj][2], c0f),     kv[1]);
        fold3f(pack_keyf(accQ[0][jj][3], c0f + 1), kv[1]);
        fold3f(pack_keyf(accQ[1][jj][0], c0f),     kv[2]);
        fold3f(pack_keyf(accQ[1][jj][1], c0f + 1), kv[2]);
        fold3f(pack_keyf(accQ[1][jj][2], c0f),     kv[3]);
        fold3f(pack_keyf(accQ[1][jj][3], c0f + 1), kv[3]);
    }

    // ---- CTA merge: 24 keys/row -> top-8 keys ----
    __syncthreads();
    float* skey = (float*)smem;                  // [128][24] = 12288 B
#pragma unroll
    for (int s4 = 0; s4 < 4; ++s4) {
        const int r = wm * 32 + (s4 >> 1) * 16 + (s4 & 1) * 8 + g;
        const int slot = (wn * 4 + tig) * 3;
#pragma unroll
        for (int s = 0; s < 3; ++s) skey[r * 24 + slot + s] = kv[s4][s];
    }
    __syncthreads();

    if (tid < 128) {
        const int r = tid;
        float v[8];
#pragma unroll
        for (int s = 0; s < 8; ++s) v[s] = NEG_SENT;
#pragma unroll 1
        for (int q = 0; q < 24; ++q) insk8f(skey[r * 24 + q], v);
        const size_t base = ((size_t)(row0 + r) * NGROUPS + blockIdx.y) * CAND;
#pragma unroll
        for (int s = 0; s < 8; ++s) g_ckey[base + s] = v[s];
    }
}

// ---------------------------------------------------------------------------
// 3) finalize: stage-1 merge 128->64, 64-thread rank-select top-8,
//    exact fp32 rescore, softmax identity
// ---------------------------------------------------------------------------
__global__ void __launch_bounds__(128)
finalize_kernel(const float* __restrict__ x, const float* __restrict__ cb,
                float* __restrict__ out) {
    const int row = blockIdx.x;
    const int tid = threadIdx.x;
    const int wid = tid >> 5, lid = tid & 31;

    __shared__ float sk[NGROUPS * CAND];         // 128 keys
    __shared__ float s2v[64];
    __shared__ int   s2i[64];
    __shared__ int   pick[8];
    __shared__ float sex[8];
    __shared__ float sw[4];
    __shared__ int   sid[3];

    const size_t cbase = (size_t)row * NGROUPS * CAND;
    sk[tid] = g_ckey[cbase + tid];
    __syncthreads();

    // stage 1: 8 lanes of warp 0 reduce 16 keys each -> top-8 (key, code)
    if (wid == 0 && lid < 8) {
        float v[8]; int ix[8];
#pragma unroll
        for (int s = 0; s < 8; ++s) { v[s] = NEG_SENT; ix[s] = 0; }
#pragma unroll 1
        for (int q = lid; q < NGROUPS * CAND; q += 8) {
            const float k = sk[q];
            const int code = (q >> 3) * GROUP_CODES + (int)(__float_as_uint(k) & 1023u);
            insp8f(k, code, v, ix);
        }
#pragma unroll
        for (int s = 0; s < 8; ++s) { s2v[lid * 8 + s] = v[s]; s2i[lid * 8 + s] = ix[s]; }
    }
    __syncthreads();

    // stage 2: 64-thread parallel rank-select over the 64 survivors.
    // Unique ranks via slot-index tie-break; rank<8 scatters into pick[].
    if (tid < 64) {
        const float kme = s2v[tid];
        int rank = 0;
#pragma unroll 8
        for (int q = 0; q < 64; ++q) {
            const float kq = s2v[q];
            rank += (int)((kq > kme) | ((kq == kme) & (q < tid)));
        }
        if (rank < CAND) pick[rank] = s2i[tid];
    }
    __syncthreads();

    // exact fp32 rescore: warp w handles candidates 2w, 2w+1
    const float4 xa = ((const float4*)(x + (size_t)row * DIM))[lid];
#pragma unroll
    for (int t = 0; t < 2; ++t) {
        const int cc = wid * 2 + t;
        const int c = pick[cc];
        const float4 ca = ((const float4*)(cb + (size_t)c * DIM))[lid];
        float p = xa.x * ca.x;
        p = fmaf(xa.y, ca.y, p);
        p = fmaf(xa.z, ca.z, p);
        p = fmaf(xa.w, ca.w, p);
#pragma unroll
        for (int o = 16; o > 0; o >>= 1) p += __shfl_xor_sync(0xFFFFFFFFu, p, o);
        if (lid == 0) sex[cc] = p;
    }
    __syncthreads();

    if (tid == 0) {
        float v[3] = { NEG_SENT, NEG_SENT, NEG_SENT };
        int ix[3] = { 0, 0, 0 };
#pragma unroll
        for (int q = 0; q < 8; ++q) ins3f(sex[q], pick[q], v, ix);
        const float INV_TAU = 100.0f;
        const float m  = fmaxf(v[0], 0.0f);
        const float w0 = expf((v[0] - m) * INV_TAU);
        const float w1 = expf((v[1] - m) * INV_TAU);
        const float w2 = expf((v[2] - m) * INV_TAU);
        const float b  = expf(-m * INV_TAU);
        const float Z  = w0 + w1 + w2 + b * (float)(N_CODES - TOPK);
        const float invZ = 1.0f / Z;
        sw[0] = w0 * invZ; sw[1] = w1 * invZ; sw[2] = w2 * invZ; sw[3] = b * invZ;
        sid[0] = ix[0]; sid[1] = ix[1]; sid[2] = ix[2];
    }
    __syncthreads();

    const int d = tid;
    const float c0 = cb[(size_t)sid[0] * DIM + d];
    const float c1 = cb[(size_t)sid[1] * DIM + d];
    const float c2 = cb[(size_t)sid[2] * DIM + d];
    out[(size_t)row * DIM + d] =
        sw[0] * c0 + sw[1] * c1 + sw[2] * c2 + sw[3] * (g_cbsum[d] - c0 - c1 - c2);
}

// ---------------------------------------------------------------------------
extern "C" void kernel_launch(void* const* d_in, const int* in_sizes, int n_in,
                              void* d_out, int out_size) {
    const float* x  = (const float*)d_in[0];
    const float* cb = (const float*)d_in[1];
    if (n_in >= 2 && in_sizes[0] == N_CODES * DIM && in_sizes[1] == N_ROWS * DIM) {
        x  = (const float*)d_in[1];
        cb = (const float*)d_in[0];
    }
    float* out = (float*)d_out;

    cudaFuncSetAttribute(gemm_topk_kernel,
                         cudaFuncAttributeMaxDynamicSharedMemorySize, GEMM_SMEM);

    __nv_bfloat16 *xb_p, *cbb_p;
    cudaGetSymbolAddress((void**)&xb_p, g_xb);
    cudaGetSymbolAddress((void**)&cbb_p, g_cbb);

    convert_all_kernel<<<1152, 256>>>(x, cb);
    cbsum_comb_kernel<<<1, 128>>>();
    gemm_topk_kernel<<<dim3(MTILES, NGROUPS), 256, GEMM_SMEM>>>(xb_p, cbb_p);
    finalize_kernel<<<N_ROWS, 128>>>(x, cb, out);
}

// round 16
// speedup vs baseline: 1.7891x; 1.1047x over previous
#include <cuda_runtime.h>
#include <cuda_bf16.h>
#include <cstdint>

// ============================================================================
// MeToken: z_q = softmax(topk3_gated(x @ cb^T) / 0.01) @ cb
//
// Identity (non-topk gated scores are 0, not -inf):
//   m = max(top1, 0), w_k = exp((s_k-m)/tau), b = exp(-m/tau)
//   Z   = w0+w1+w2 + (C-K)*b
//   z_q = (w0*cb0 + w1*cb1 + w2*cb2 + b*(colsum(cb) - cb0-cb1-cb2)) / Z
//
// R16 = R15 GEMM + CAND 8->4 (global top-3 is always within its group's
// top-3, so per-group top-4 preserves screening correctness) which lets
// finalize drop stage-1 entirely: one 64-thread rank-select over 64 keys
// -> top-8 pool -> exact fp32 rescore -> softmax identity.
// ============================================================================

#define N_ROWS 8192
#define DIM 128
#define N_CODES 16384
#define TOPK 3

#define MT 128
#define NT 128                          // codes per B-subtile
#define TILES_PER_GROUP 8
#define GROUP_CODES (NT * TILES_PER_GROUP)   // 1024
#define NGROUPS (N_CODES / GROUP_CODES)      // 16
#define MTILES (N_ROWS / MT)                 // 64
#define CAND 4                          // per-group survivors
#define POOL 8                          // rescore pool size
#define STRIDE_B 272                    // bytes per smem row (136 bf16)
#define A_BYTES (128 * STRIDE_B)        // 34816
#define B_BYTES (128 * STRIDE_B)        // 34816
#define GEMM_SMEM (A_BYTES + 2 * B_BYTES)    // 104448

#define NEG_SENT (-3.0e38f)

// ---------------- scratch (no allocs allowed) ----------------
__device__ __nv_bfloat16 g_xb[N_ROWS * DIM];
__device__ __nv_bfloat16 g_cbb[N_CODES * DIM];
__device__ float g_part_cbsum[256 * DIM];
__device__ float g_cbsum[DIM];
__device__ float g_ckey[(size_t)N_ROWS * NGROUPS * CAND];   // float keys (idx in low bits)

// ---------------- helpers ----------------
__device__ __forceinline__ uint32_t smem_u32(const void* p) {
    uint32_t a;
    asm("{ .reg .u64 t; cvta.to.shared.u64 t, %1; cvt.u32.u64 %0, t; }" : "=r"(a) : "l"(p));
    return a;
}
__device__ __forceinline__ void cp_async16(uint32_t dst, const void* src) {
    asm volatile("cp.async.cg.shared.global [%0], [%1], 16;" :: "r"(dst), "l"(src) : "memory");
}
__device__ __forceinline__ void cp_commit() {
    asm volatile("cp.async.commit_group;" ::: "memory");
}
__device__ __forceinline__ void cp_wait1() {
    asm volatile("cp.async.wait_group 1;" ::: "memory");
}
__device__ __forceinline__ void cp_wait0() {
    asm volatile("cp.async.wait_group 0;" ::: "memory");
}
__device__ __forceinline__ void ldsm_x4(uint32_t& r0, uint32_t& r1, uint32_t& r2, uint32_t& r3,
                                        uint32_t addr) {
    asm volatile("ldmatrix.sync.aligned.m8n8.x4.shared.b16 {%0,%1,%2,%3}, [%4];"
                 : "=r"(r0), "=r"(r1), "=r"(r2), "=r"(r3) : "r"(addr));
}
__device__ __forceinline__ void mma16816(float c[4], const uint32_t a[4], const uint32_t b[2]) {
    asm volatile(
        "mma.sync.aligned.m16n8k16.row.col.f32.bf16.bf16.f32 "
        "{%0,%1,%2,%3}, {%4,%5,%6,%7}, {%8,%9}, {%0,%1,%2,%3};"
        : "+f"(c[0]), "+f"(c[1]), "+f"(c[2]), "+f"(c[3])
        : "r"(a[0]), "r"(a[1]), "r"(a[2]), "r"(a[3]), "r"(b[0]), "r"(b[1]));
}

// float key: low 10 mantissa bits replaced by group-local code index (1 LOP3)
__device__ __forceinline__ float pack_keyf(float s, int lidx) {
    return __uint_as_float((__float_as_uint(s) & 0xFFFFFC00u) | (uint32_t)lidx);
}
// branchless top-3 fold: 5 FMNMX, no branches
__device__ __forceinline__ void fold3f(float k, float v[3]) {
    const float t0 = fmaxf(v[0], k);
    const float m0 = fminf(v[0], k);
    const float t1 = fmaxf(v[1], m0);
    const float m1 = fminf(v[1], m0);
    const float t2 = fmaxf(v[2], m1);
    v[0] = t0; v[1] = t1; v[2] = t2;
}
// branchy 4-deep insert (GEMM CTA merge)
__device__ __forceinline__ void insk4f(float k, float v[4]) {
    if (k <= v[3]) return;
    v[3] = k;
#pragma unroll
    for (int t = 3; t > 0; --t)
        if (v[t] > v[t - 1]) { float tv = v[t]; v[t] = v[t - 1]; v[t - 1] = tv; }
}
__device__ __forceinline__ void ins3f(float s, int c, float v[3], int ix[3]) {
    if (s > v[2]) {
        if (s > v[1]) {
            v[2] = v[1]; ix[2] = ix[1];
            if (s > v[0]) { v[1] = v[0]; ix[1] = ix[0]; v[0] = s; ix[0] = c; }
            else          { v[1] = s;    ix[1] = c; }
        } else { v[2] = s; ix[2] = c; }
    }
}

// ---------------------------------------------------------------------------
// 1) fused converts (+ cb partial column sums)
// ---------------------------------------------------------------------------
__global__ void __launch_bounds__(256)
convert_all_kernel(const float* __restrict__ x, const float* __restrict__ cb) {
    if (blockIdx.x < 1024) {
        const int i = (blockIdx.x * 256 + threadIdx.x) * 4;
        const float4 v = *(const float4*)(x + i);
        __nv_bfloat162* o = (__nv_bfloat162*)(g_xb + i);
        o[0] = __nv_bfloat162(__float2bfloat16_rn(v.x), __float2bfloat16_rn(v.y));
        o[1] = __nv_bfloat162(__float2bfloat16_rn(v.z), __float2bfloat16_rn(v.w));
    } else {
        const int b = blockIdx.x - 1024;          // 128 cb blocks, 128 codes each
        const int d = threadIdx.x & 127;          // column
        const int h = threadIdx.x >> 7;           // half: rows [h*64, h*64+64)
        const float* p = cb + ((size_t)b * 128 + h * 64) * DIM + d;
        __nv_bfloat16* q = g_cbb + ((size_t)b * 128 + h * 64) * DIM + d;
        float s = 0.0f;
#pragma unroll 8
        for (int c = 0; c < 64; ++c) {
            const float v = p[(size_t)c * DIM];
            s += v;
            q[(size_t)c * DIM] = __float2bfloat16_rn(v);
        }
        g_part_cbsum[(b * 2 + h) * DIM + d] = s;
    }
}
__global__ void cbsum_comb_kernel() {
    const int d = threadIdx.x;
    float s = 0.0f;
#pragma unroll 8
    for (int b = 0; b < 256; ++b) s += g_part_cbsum[b * DIM + d];
    g_cbsum[d] = s;
}

// ---------------------------------------------------------------------------
// 2) multi-tile mma.sync GEMM, 2 CTAs/SM, half-phase fold overlap (R13)
// ---------------------------------------------------------------------------
__global__ void __launch_bounds__(256, 2)
gemm_topk_kernel(const __nv_bfloat16* __restrict__ xb,
                 const __nv_bfloat16* __restrict__ cbb) {
    extern __shared__ __align__(16) char smem[];
    const uint32_t sbase = smem_u32(smem);
    const uint32_t sA = sbase;
    const uint32_t sB[2] = { sbase + A_BYTES, sbase + A_BYTES + B_BYTES };

    const int tid = threadIdx.x;
    const int wid = tid >> 5, lane = tid & 31;
    const int g = lane >> 2, tig = lane & 3;
    const int wm = wid & 3, wn = wid >> 2;       // 4M x 2N

    const int row0  = blockIdx.x * MT;
    const int code0 = blockIdx.y * GROUP_CODES;

    const uint4* gx = (const uint4*)(xb + (size_t)row0 * DIM);
    const uint4* gc = (const uint4*)(cbb + (size_t)code0 * DIM);

    // ---- prologue: A + B0 ----
#pragma unroll
    for (int i = tid; i < 128 * 16; i += 256) {
        const int r = i >> 4, kc = i & 15;
        cp_async16(sA + r * STRIDE_B + kc * 16, gx + r * 16 + kc);
    }
#pragma unroll
    for (int i = tid; i < 128 * 16; i += 256) {
        const int r = i >> 4, kc = i & 15;
        cp_async16(sB[0] + r * STRIDE_B + kc * 16, gc + r * 16 + kc);
    }
    cp_commit();

    // float top-3 keys for 4 owned rows
    float kv[4][3];
#pragma unroll
    for (int t = 0; t < 4; ++t)
#pragma unroll
        for (int s = 0; s < 3; ++s) kv[t][s] = NEG_SENT;

    // ldmatrix per-lane addressing
    const int aq = lane >> 3;
    const uint32_t fragRow = (uint32_t)((lane & 7) + (aq & 1) * 8);
    const uint32_t fragCol = (uint32_t)((aq >> 1) * 16);
    const uint32_t aOff = (uint32_t)(wm * 32) * STRIDE_B + fragRow * STRIDE_B + fragCol;
    const uint32_t bFragRow = (uint32_t)((lane & 7) + (aq >> 1) * 8);
    const uint32_t bFragCol = (uint32_t)((aq & 1) * 16);
    const uint32_t bOff = (uint32_t)(wn * 64) * STRIDE_B + bFragRow * STRIDE_B + bFragCol;
    const int colb = wn * 64 + tig * 2;          // lane's column base within tile

    // two half-tile accumulator banks (32 scores each), ping-ponged
    float accP[2][4][4], accQ[2][4][4];

#define HALF_PHASE(T, H, CUR, PREV, PBASE, DOFOLD)                             \
    {                                                                          \
        _Pragma("unroll")                                                      \
        for (int i = 0; i < 2; ++i)                                            \
            _Pragma("unroll")                                                  \
            for (int jj = 0; jj < 4; ++jj)                                     \
                _Pragma("unroll")                                              \
                for (int c = 0; c < 4; ++c) CUR[i][jj][c] = 0.0f;              \
        const uint32_t aBt = sA + aOff;                                        \
        const uint32_t bBt = sB[(T) & 1] + bOff                                \
                           + (uint32_t)(32 * (H)) * STRIDE_B;                  \
        _Pragma("unroll")                                                      \
        for (int ks = 0; ks < 8; ++ks) {                                       \
            const uint32_t kOff = ks * 32;                                     \
            uint32_t a[2][4];                                                  \
            _Pragma("unroll")                                                  \
            for (int i = 0; i < 2; ++i)                                        \
                ldsm_x4(a[i][0], a[i][1], a[i][2], a[i][3],                    \
                        aBt + (uint32_t)(16 * i) * STRIDE_B + kOff);           \
            uint32_t b[4][2];                                                  \
            _Pragma("unroll")                                                  \
            for (int jp = 0; jp < 2; ++jp)                                     \
                ldsm_x4(b[2 * jp][0], b[2 * jp][1],                            \
                        b[2 * jp + 1][0], b[2 * jp + 1][1],                    \
                        bBt + (uint32_t)(16 * jp) * STRIDE_B + kOff);          \
            _Pragma("unroll")                                                  \
            for (int i = 0; i < 2; ++i)                                        \
                _Pragma("unroll")                                              \
                for (int jj = 0; jj < 4; ++jj)                                 \
                    mma16816(CUR[i][jj], a[i], b[jj]);                         \
            if (DOFOLD) {                                                      \
                const int fi = ks >> 2, fj = ks & 3;                           \
                const int c0f = (PBASE) + fj * 8;                              \
                fold3f(pack_keyf(PREV[fi][fj][0], c0f),     kv[2 * fi]);       \
                fold3f(pack_keyf(PREV[fi][fj][1], c0f + 1), kv[2 * fi]);       \
                fold3f(pack_keyf(PREV[fi][fj][2], c0f),     kv[2 * fi + 1]);   \
                fold3f(pack_keyf(PREV[fi][fj][3], c0f + 1), kv[2 * fi + 1]);   \
            }                                                                  \
        }                                                                      \
    }

#define TILE_STEP(T, FOLD0)                                                    \
    {                                                                          \
        __syncthreads();                                                       \
        if ((T) + 1 < TILES_PER_GROUP) {                                       \
            const uint4* gt = gc + (size_t)((T) + 1) * 2048;                   \
            const uint32_t dst = sB[((T) + 1) & 1];                            \
            _Pragma("unroll")                                                  \
            for (int i2 = tid; i2 < 2048; i2 += 256) {                         \
                const int r2 = i2 >> 4, kc2 = i2 & 15;                         \
                cp_async16(dst + r2 * STRIDE_B + kc2 * 16, gt + r2 * 16 + kc2);\
            }                                                                  \
            cp_commit(); cp_wait1();                                           \
        } else { cp_wait0(); }                                                 \
        __syncthreads();                                                       \
        HALF_PHASE(T, 0, accP, accQ, ((T) - 1) * NT + 32 + colb, FOLD0)        \
        HALF_PHASE(T, 1, accQ, accP, (T) * NT + colb, true)                    \
    }

    TILE_STEP(0, false)
    TILE_STEP(1, true)
    TILE_STEP(2, true)
    TILE_STEP(3, true)
    TILE_STEP(4, true)
    TILE_STEP(5, true)
    TILE_STEP(6, true)
    TILE_STEP(7, true)
#undef TILE_STEP
#undef HALF_PHASE

    // epilogue fold: half (7,1) lives in accQ, base = 7*NT + 32 + colb
#pragma unroll
    for (int jj = 0; jj < 4; ++jj) {
        const int c0f = 7 * NT + 32 + colb + jj * 8;
        fold3f(pack_keyf(accQ[0][jj][0], c0f),     kv[0]);
        fold3f(pack_keyf(accQ[0][jj][1], c0f + 1), kv[0]);
        fold3f(pack_keyf(accQ[0][jj][2], c0f),     kv[1]);
        fold3f(pack_keyf(accQ[0][jj][3], c0f + 1), kv[1]);
        fold3f(pack_keyf(accQ[1][jj][0], c0f),     kv[2]);
        fold3f(pack_keyf(accQ[1][jj][1], c0f + 1), kv[2]);
        fold3f(pack_keyf(accQ[1][jj][2], c0f),     kv[3]);
        fold3f(pack_keyf(accQ[1][jj][3], c0f + 1), kv[3]);
    }

    // ---- CTA merge: 24 keys/row -> top-4 keys ----
    __syncthreads();
    float* skey = (float*)smem;                  // [128][24] = 12288 B
#pragma unroll
    for (int s4 = 0; s4 < 4; ++s4) {
        const int r = wm * 32 + (s4 >> 1) * 16 + (s4 & 1) * 8 + g;
        const int slot = (wn * 4 + tig) * 3;
#pragma unroll
        for (int s = 0; s < 3; ++s) skey[r * 24 + slot + s] = kv[s4][s];
    }
    __syncthreads();

    if (tid < 128) {
        const int r = tid;
        float v[CAND];
#pragma unroll
        for (int s = 0; s < CAND; ++s) v[s] = NEG_SENT;
#pragma unroll 1
        for (int q = 0; q < 24; ++q) insk4f(skey[r * 24 + q], v);
        const size_t base = ((size_t)(row0 + r) * NGROUPS + blockIdx.y) * CAND;
#pragma unroll
        for (int s = 0; s < CAND; ++s) g_ckey[base + s] = v[s];
    }
}

// ---------------------------------------------------------------------------
// 3) finalize: 64-thread rank-select top-8 over 64 keys, exact fp32 rescore,
//    softmax identity
// ---------------------------------------------------------------------------
__global__ void __launch_bounds__(128)
finalize_kernel(const float* __restrict__ x, const float* __restrict__ cb,
                float* __restrict__ out) {
    const int row = blockIdx.x;
    const int tid = threadIdx.x;
    const int wid = tid >> 5, lid = tid & 31;

    __shared__ float sk[NGROUPS * CAND];         // 64 keys
    __shared__ int   pick[POOL];
    __shared__ float sex[POOL];
    __shared__ float sw[4];
    __shared__ int   sid[3];

    const size_t cbase = (size_t)row * NGROUPS * CAND;
    if (tid < NGROUPS * CAND) sk[tid] = g_ckey[cbase + tid];
    __syncthreads();

    // 64-thread rank-select: rank = #keys outranking mine (index tie-break).
    if (tid < NGROUPS * CAND) {
        const float kme = sk[tid];
        int rank = 0;
#pragma unroll 8
        for (int q = 0; q < NGROUPS * CAND; ++q) {
            const float kq = sk[q];
            rank += (int)((kq > kme) | ((kq == kme) & (q < tid)));
        }
        if (rank < POOL) {
            const int code = (tid >> 2) * GROUP_CODES + (int)(__float_as_uint(kme) & 1023u);
            pick[rank] = code;
        }
    }
    __syncthreads();

    // exact fp32 rescore: warp w handles candidates 2w, 2w+1
    const float4 xa = ((const float4*)(x + (size_t)row * DIM))[lid];
#pragma unroll
    for (int t = 0; t < 2; ++t) {
        const int cc = wid * 2 + t;
        const int c = pick[cc];
        const float4 ca = ((const float4*)(cb + (size_t)c * DIM))[lid];
        float p = xa.x * ca.x;
        p = fmaf(xa.y, ca.y, p);
        p = fmaf(xa.z, ca.z, p);
        p = fmaf(xa.w, ca.w, p);
#pragma unroll
        for (int o = 16; o > 0; o >>= 1) p += __shfl_xor_sync(0xFFFFFFFFu, p, o);
        if (lid == 0) sex[cc] = p;
    }
    __syncthreads();

    if (tid == 0) {
        float v[3] = { NEG_SENT, NEG_SENT, NEG_SENT };
        int ix[3] = { 0, 0, 0 };
#pragma unroll
        for (int q = 0; q < POOL; ++q) ins3f(sex[q], pick[q], v, ix);
        const float INV_TAU = 100.0f;
        const float m  = fmaxf(v[0], 0.0f);
        const float w0 = expf((v[0] - m) * INV_TAU);
        const float w1 = expf((v[1] - m) * INV_TAU);
        const float w2 = expf((v[2] - m) * INV_TAU);
        const float b  = expf(-m * INV_TAU);
        const float Z  = w0 + w1 + w2 + b * (float)(N_CODES - TOPK);
        const float invZ = 1.0f / Z;
        sw[0] = w0 * invZ; sw[1] = w1 * invZ; sw[2] = w2 * invZ; sw[3] = b * invZ;
        sid[0] = ix[0]; sid[1] = ix[1]; sid[2] = ix[2];
    }
    __syncthreads();

    const int d = tid;
    const float c0 = cb[(size_t)sid[0] * DIM + d];
    const float c1 = cb[(size_t)sid[1] * DIM + d];
    const float c2 = cb[(size_t)sid[2] * DIM + d];
    out[(size_t)row * DIM + d] =
        sw[0] * c0 + sw[1] * c1 + sw[2] * c2 + sw[3] * (g_cbsum[d] - c0 - c1 - c2);
}

// ---------------------------------------------------------------------------
extern "C" void kernel_launch(void* const* d_in, const int* in_sizes, int n_in,
                              void* d_out, int out_size) {
    const float* x  = (const float*)d_in[0];
    const float* cb = (const float*)d_in[1];
    if (n_in >= 2 && in_sizes[0] == N_CODES * DIM && in_sizes[1] == N_ROWS * DIM) {
        x  = (const float*)d_in[1];
        cb = (const float*)d_in[0];
    }
    float* out = (float*)d_out;

    cudaFuncSetAttribute(gemm_topk_kernel,
                         cudaFuncAttributeMaxDynamicSharedMemorySize, GEMM_SMEM);

    __nv_bfloat16 *xb_p, *cbb_p;
    cudaGetSymbolAddress((void**)&xb_p, g_xb);
    cudaGetSymbolAddress((void**)&cbb_p, g_cbb);

    convert_all_kernel<<<1152, 256>>>(x, cb);
    cbsum_comb_kernel<<<1, 128>>>();
    gemm_topk_kernel<<<dim3(MTILES, NGROUPS), 256, GEMM_SMEM>>>(xb_p, cbb_p);
    finalize_kernel<<<N_ROWS, 128>>>(x, cb, out);
}